// round 6
// baseline (speedup 1.0000x reference)
#include <cuda_runtime.h>
#include <cuda_bf16.h>

// out[b,h,i,j] = mask[b,h,i,j] - |slope(h) * (i - j)|
// B=2, NH=16, L=2048. HBM-bound: 512 MiB read + 512 MiB write.
//
// R5: persistent grid-stride variant of R3 (the best config):
//   - 296 blocks = 148 SMs x 2 resident (regs<=48, 512 thr) -> zero tail imbalance
//   - 8 contiguous rows per iteration (64KB contiguous block footprint)
//   - front-batched 8 independent LDG.128 per thread (MLP_p1=8)
//   - streaming hints (zero-reuse data)

#define ROWS_PER_IT 8
#define NBLOCKS 296

__global__ __launch_bounds__(512) void alibi_kernel(
    const float4* __restrict__ m4,
    float4* __restrict__ o4,
    int ngroups)                        // total row-groups = 65536/8 = 8192
{
    const int t  = threadIdx.x;         // 0..511
    const int j0 = t * 4;
    const float fj0 = (float)(j0 + 0);
    const float fj1 = (float)(j0 + 1);
    const float fj2 = (float)(j0 + 2);
    const float fj3 = (float)(j0 + 3);

    for (int grp = blockIdx.x; grp < ngroups; grp += NBLOCKS) {
        const int rb = grp * ROWS_PER_IT;       // base row, shares (b,h) across 8 rows
        const int i0 = rb & 2047;               // rb % L
        const int h  = (rb >> 11) & 15;         // (rb / L) % NH

        const float slope = exp2f(-0.5f * (float)(h + 1));

        const long long base4 = (long long)rb * 512;   // rows are 512 float4 long
        const float4* __restrict__ mrow = m4 + base4;
        float4*       __restrict__ orow = o4 + base4;

        // Front-batched independent streaming loads.
        float4 m[ROWS_PER_IT];
        #pragma unroll
        for (int r = 0; r < ROWS_PER_IT; r++)
            m[r] = __ldcs(&mrow[r * 512 + t]);

        #pragma unroll
        for (int r = 0; r < ROWS_PER_IT; r++) {
            const float fi = (float)(i0 + r);
            float4 o;
            o.x = m[r].x - slope * fabsf(fi - fj0);
            o.y = m[r].y - slope * fabsf(fi - fj1);
            o.z = m[r].z - slope * fabsf(fi - fj2);
            o.w = m[r].w - slope * fabsf(fi - fj3);
            __stcs(&orow[r * 512 + t], o);
        }
    }
}

extern "C" void kernel_launch(void* const* d_in, const int* in_sizes, int n_in,
                              void* d_out, int out_size)
{
    const float4* mask = (const float4*)d_in[0];
    float4* out = (float4*)d_out;

    const int L = 2048;
    const long long total = (long long)in_sizes[0];   // B*NH*L*L
    const int rows = (int)(total / L);                // 65536
    const int ngroups = rows / ROWS_PER_IT;           // 8192

    alibi_kernel<<<NBLOCKS, 512>>>(mask, out, ngroups);
}

// round 7
// speedup vs baseline: 1.0792x; 1.0792x over previous
#include <cuda_runtime.h>
#include <cuda_bf16.h>

// out[b,h,i,j] = mask[b,h,i,j] - |slope(h) * (i - j)|
// B=2, NH=16, L=2048. HBM-bound: 512 MiB read + 512 MiB write.
//
// R6: revert to R3 (empirical best: 149.4us ncu, DRAM 86.0%):
//   - 8 contiguous rows per block, 512 threads, one float4 per thread per row
//   - front-batched 8 independent LDG.128 (MLP_p1=8)
//   - __ldcg loads (L2-only; zero L1 reuse), __stcs stores (evict-first)
//   - non-persistent: 8192 fire-and-forget blocks overlap loads/stores
//     across block waves (persistent variant measured worse).

#define ROWS_PER_BLK 8

__global__ __launch_bounds__(512, 2) void alibi_kernel(
    const float* __restrict__ mask,
    float* __restrict__ out,
    int L)
{
    // Base row for this block; all 8 rows share (b,h) since L % 8 == 0.
    const int rb = blockIdx.x * ROWS_PER_BLK;
    const int i0 = rb & (2048 - 1);          // rb % L, L=2048
    const int h  = (rb >> 11) & 15;          // (rb / L) % NH

    // slope = 2^(-0.5*(h+1))  (NH=16 is a power of two)
    const float slope = exp2f(-0.5f * (float)(h + 1));

    const int t  = threadIdx.x;              // 0..511
    const int j0 = t * 4;

    const long long base = (long long)rb * (long long)L;
    const float4* __restrict__ m4 = (const float4*)(mask + base);
    float4*       __restrict__ o4 = (float4*)(out + base);

    // Front-batched independent loads (rows are 512 float4 apart).
    float4 m[ROWS_PER_BLK];
    #pragma unroll
    for (int r = 0; r < ROWS_PER_BLK; r++)
        m[r] = __ldcg(&m4[r * 512 + t]);

    #pragma unroll
    for (int r = 0; r < ROWS_PER_BLK; r++) {
        const float fi = (float)(i0 + r);
        float4 o;
        o.x = m[r].x - slope * fabsf(fi - (float)(j0 + 0));
        o.y = m[r].y - slope * fabsf(fi - (float)(j0 + 1));
        o.z = m[r].z - slope * fabsf(fi - (float)(j0 + 2));
        o.w = m[r].w - slope * fabsf(fi - (float)(j0 + 3));
        __stcs(&o4[r * 512 + t], o);
    }
}

extern "C" void kernel_launch(void* const* d_in, const int* in_sizes, int n_in,
                              void* d_out, int out_size)
{
    const float* mask = (const float*)d_in[0];
    float* out = (float*)d_out;

    const int L = 2048;
    const long long total = (long long)in_sizes[0];        // B*NH*L*L
    const int rows = (int)(total / L);                     // 65536
    const int blocks = rows / ROWS_PER_BLK;                // 8192

    alibi_kernel<<<blocks, 512>>>(mask, out, L);
}

// round 9
// speedup vs baseline: 1.0969x; 1.0164x over previous
#include <cuda_runtime.h>
#include <cuda_bf16.h>

// out[b,h,i,j] = mask[b,h,i,j] - |slope(h) * (i - j)|
// B=2, NH=16, L=2048. HBM-bound: 512 MiB read + 512 MiB write.
//
// R7 = exact revert to R3, the empirical best (149.4us ncu, DRAM 86.0%,
// 156.9us harness). All perturbations tried (flat-stride 256t, persistent
// grid, __ldcg, __launch_bounds__(512,2)) measured strictly worse:
// this configuration sits at the mixed read+write HBM turnaround ceiling.
//
//   - 8 contiguous rows per block (64KB contiguous footprint), 512 threads
//   - front-batched 8 independent LDG.128 per thread (MLP_p1=8)
//   - __ldcs / __stcs streaming hints (zero-reuse data)
//   - non-persistent fire-and-forget blocks: wave transitions overlap the
//     next block's loads with the previous block's in-flight stores.

#define ROWS_PER_BLK 8

__global__ __launch_bounds__(512) void alibi_kernel(
    const float* __restrict__ mask,
    float* __restrict__ out,
    int L)
{
    // Base row for this block; all 8 rows share (b,h) since L % 8 == 0.
    const int rb = blockIdx.x * ROWS_PER_BLK;
    const int i0 = rb & (2048 - 1);          // rb % L, L=2048
    const int h  = (rb >> 11) & 15;          // (rb / L) % NH

    // slope = 2^(-0.5*(h+1))  (NH=16 is a power of two)
    const float slope = exp2f(-0.5f * (float)(h + 1));

    const int t  = threadIdx.x;              // 0..511
    const int j0 = t * 4;

    const long long base = (long long)rb * (long long)L;
    const float4* __restrict__ m4 = (const float4*)(mask + base);
    float4*       __restrict__ o4 = (float4*)(out + base);

    // Front-batched independent streaming loads (rows are 512 float4 apart).
    float4 m[ROWS_PER_BLK];
    #pragma unroll
    for (int r = 0; r < ROWS_PER_BLK; r++)
        m[r] = __ldcs(&m4[r * 512 + t]);

    #pragma unroll
    for (int r = 0; r < ROWS_PER_BLK; r++) {
        const float fi = (float)(i0 + r);
        float4 o;
        o.x = m[r].x - slope * fabsf(fi - (float)(j0 + 0));
        o.y = m[r].y - slope * fabsf(fi - (float)(j0 + 1));
        o.z = m[r].z - slope * fabsf(fi - (float)(j0 + 2));
        o.w = m[r].w - slope * fabsf(fi - (float)(j0 + 3));
        __stcs(&o4[r * 512 + t], o);
    }
}

extern "C" void kernel_launch(void* const* d_in, const int* in_sizes, int n_in,
                              void* d_out, int out_size)
{
    const float* mask = (const float*)d_in[0];
    float* out = (float*)d_out;

    const int L = 2048;
    const long long total = (long long)in_sizes[0];        // B*NH*L*L
    const int rows = (int)(total / L);                     // 65536
    const int blocks = rows / ROWS_PER_BLK;                // 8192

    alibi_kernel<<<blocks, 512>>>(mask, out, L);
}